// round 1
// baseline (speedup 1.0000x reference)
#include <cuda_runtime.h>
#include <cuda_bf16.h>
#include <cstdint>

// Problem constants
constexpr int T_DIM = 256;
constexpr int B_DIM = 256;
constexpr int IN_DIM = 1024;
constexpr int H_DIM = 1024;
constexpr int M1 = T_DIM * B_DIM;   // 65536 rows for phase-1 GEMM

// Split-K partial buffers for the recurrence GEMM (2 slabs of [B, H])
__device__ float g_part[2][B_DIM * H_DIM];

// ---------------------------------------------------------------------------
// Packed f32x2 helpers (Blackwell FFMA2 — double-rate fp32)
// ---------------------------------------------------------------------------
__device__ __forceinline__ unsigned long long pack2(float lo, float hi) {
    unsigned long long r;
    asm("mov.b64 %0, {%1, %2};" : "=l"(r) : "f"(lo), "f"(hi));
    return r;
}
__device__ __forceinline__ unsigned long long ffma2(unsigned long long a,
                                                    unsigned long long b,
                                                    unsigned long long c) {
    unsigned long long d;
    asm("fma.rn.f32x2 %0, %1, %2, %3;" : "=l"(d) : "l"(a), "l"(b), "l"(c));
    return d;
}
__device__ __forceinline__ float2 unpack2(unsigned long long v) {
    float2 f;
    asm("mov.b64 {%0, %1}, %2;" : "=f"(f.x), "=f"(f.y) : "l"(v));
    return f;
}

// ---------------------------------------------------------------------------
// Phase 1: xi[m, n] = sum_k x[m,k] * Wi[n,k] + bi[n]
// M=65536, N=1024, K=1024.  BM=BN=128, BK=8, 256 threads, 8x8 per thread.
// Writes directly into d_out (xi occupies the same [T,B,H] layout).
// ---------------------------------------------------------------------------
__global__ __launch_bounds__(256) void gemm_xi_kernel(
    const float* __restrict__ A,     // x  [M1, IN]
    const float* __restrict__ Bw,    // Wi [H, IN]
    const float* __restrict__ bias,  // bi [H]
    float* __restrict__ C)           // xi -> d_out [M1, H]
{
    __shared__ float As[8][128];
    __shared__ float Bs[8][128];

    const int tid = threadIdx.x;
    const int m0 = blockIdx.y * 128;
    const int n0 = blockIdx.x * 128;
    const int tx = tid & 15;   // column group: 8 cols each
    const int ty = tid >> 4;   // row group:    8 rows each
    const int lr = tid >> 1;   // load row within tile (0..127)
    const int lc = (tid & 1) * 4;  // load col offset (0 or 4)

    unsigned long long acc[8][4];
#pragma unroll
    for (int i = 0; i < 8; i++)
#pragma unroll
        for (int j = 0; j < 4; j++) acc[i][j] = 0ull;

    const float* aLoad = A + (size_t)(m0 + lr) * IN_DIM + lc;
    const float* bLoad = Bw + (size_t)(n0 + lr) * IN_DIM + lc;

    for (int k0 = 0; k0 < IN_DIM; k0 += 8) {
        float4 av = *reinterpret_cast<const float4*>(aLoad + k0);
        float4 bv = *reinterpret_cast<const float4*>(bLoad + k0);
        As[lc + 0][lr] = av.x; As[lc + 1][lr] = av.y;
        As[lc + 2][lr] = av.z; As[lc + 3][lr] = av.w;
        Bs[lc + 0][lr] = bv.x; Bs[lc + 1][lr] = bv.y;
        Bs[lc + 2][lr] = bv.z; Bs[lc + 3][lr] = bv.w;
        __syncthreads();

#pragma unroll
        for (int k = 0; k < 8; k++) {
            float4 a0 = *reinterpret_cast<const float4*>(&As[k][ty * 8]);
            float4 a1 = *reinterpret_cast<const float4*>(&As[k][ty * 8 + 4]);
            ulonglong2 b01 = *reinterpret_cast<const ulonglong2*>(&Bs[k][tx * 8]);
            ulonglong2 b23 = *reinterpret_cast<const ulonglong2*>(&Bs[k][tx * 8 + 4]);
            float a[8] = {a0.x, a0.y, a0.z, a0.w, a1.x, a1.y, a1.z, a1.w};
#pragma unroll
            for (int i = 0; i < 8; i++) {
                unsigned long long a2 = pack2(a[i], a[i]);
                acc[i][0] = ffma2(a2, b01.x, acc[i][0]);
                acc[i][1] = ffma2(a2, b01.y, acc[i][1]);
                acc[i][2] = ffma2(a2, b23.x, acc[i][2]);
                acc[i][3] = ffma2(a2, b23.y, acc[i][3]);
            }
        }
        __syncthreads();
    }

    // Epilogue: add bias, store
    float bb[8];
#pragma unroll
    for (int j = 0; j < 8; j++) bb[j] = bias[n0 + tx * 8 + j];

#pragma unroll
    for (int i = 0; i < 8; i++) {
        float c[8];
#pragma unroll
        for (int j = 0; j < 4; j++) {
            float2 v = unpack2(acc[i][j]);
            c[2 * j + 0] = v.x + bb[2 * j + 0];
            c[2 * j + 1] = v.y + bb[2 * j + 1];
        }
        float* cp = C + (size_t)(m0 + ty * 8 + i) * H_DIM + n0 + tx * 8;
        *reinterpret_cast<float4*>(cp + 0) = make_float4(c[0], c[1], c[2], c[3]);
        *reinterpret_cast<float4*>(cp + 4) = make_float4(c[4], c[5], c[6], c[7]);
    }
}

// ---------------------------------------------------------------------------
// Phase 2a: per-step recurrence GEMM, split-K=2.
// part[z][m, n] = sum_{k in half z} h_prev[m,k] * Wh[n,k]
// M=256, N=1024, K halves of 512.  BM=BN=64, BK=8, 256 threads, 4x4/thread.
// Grid (16, 4, 2)
// ---------------------------------------------------------------------------
__global__ __launch_bounds__(256) void gemm_h_kernel(
    const float* __restrict__ Hprev,  // [B, H]
    const float* __restrict__ W)      // Wh [H, H]
{
    __shared__ float As[8][64];
    __shared__ float Bs[8][64];

    const int tid = threadIdx.x;
    const int m0 = blockIdx.y * 64;
    const int n0 = blockIdx.x * 64;
    const int kz = blockIdx.z;
    const int kbase = kz * 512;

    const int tx = tid & 15;   // column group: 4 cols each
    const int ty = tid >> 4;   // row group:    4 rows each
    const int lr = tid >> 2;         // 0..63
    const int lc = (tid & 3) * 2;    // 0,2,4,6

    unsigned long long acc[4][2];
#pragma unroll
    for (int i = 0; i < 4; i++) { acc[i][0] = 0ull; acc[i][1] = 0ull; }

    const float* aLoad = Hprev + (size_t)(m0 + lr) * H_DIM + lc;
    const float* bLoad = W + (size_t)(n0 + lr) * H_DIM + lc;

    for (int k0 = kbase; k0 < kbase + 512; k0 += 8) {
        float2 av = *reinterpret_cast<const float2*>(aLoad + k0);
        float2 bv = *reinterpret_cast<const float2*>(bLoad + k0);
        As[lc + 0][lr] = av.x; As[lc + 1][lr] = av.y;
        Bs[lc + 0][lr] = bv.x; Bs[lc + 1][lr] = bv.y;
        __syncthreads();

#pragma unroll
        for (int k = 0; k < 8; k++) {
            float4 a = *reinterpret_cast<const float4*>(&As[k][ty * 4]);
            ulonglong2 b = *reinterpret_cast<const ulonglong2*>(&Bs[k][tx * 4]);
            float av4[4] = {a.x, a.y, a.z, a.w};
#pragma unroll
            for (int i = 0; i < 4; i++) {
                unsigned long long a2 = pack2(av4[i], av4[i]);
                acc[i][0] = ffma2(a2, b.x, acc[i][0]);
                acc[i][1] = ffma2(a2, b.y, acc[i][1]);
            }
        }
        __syncthreads();
    }

#pragma unroll
    for (int i = 0; i < 4; i++) {
        float2 v0 = unpack2(acc[i][0]);
        float2 v1 = unpack2(acc[i][1]);
        float* pp = &g_part[kz][(size_t)(m0 + ty * 4 + i) * H_DIM + n0 + tx * 4];
        *reinterpret_cast<float4*>(pp) = make_float4(v0.x, v0.y, v1.x, v1.y);
    }
}

// ---------------------------------------------------------------------------
// Phase 2b: epilogue.  h_t = tanh(part0 + part1 + xi_t + bh), in place on d_out
// 256 blocks x 256 threads x 4 elems = 262144 elems
// ---------------------------------------------------------------------------
__global__ __launch_bounds__(256) void step_epilogue_kernel(
    const float* __restrict__ xi,   // d_out + t*B*H (holds xi_t)
    const float* __restrict__ bh,   // Wh_b [H]
    float* __restrict__ hout)       // same location: overwritten with h_t
{
    const int idx = (blockIdx.x * blockDim.x + threadIdx.x) * 4;
    float4 p0 = *reinterpret_cast<const float4*>(&g_part[0][idx]);
    float4 p1 = *reinterpret_cast<const float4*>(&g_part[1][idx]);
    float4 xv = *reinterpret_cast<const float4*>(&xi[idx]);
    const int n = idx & (H_DIM - 1);
    float4 bb = *reinterpret_cast<const float4*>(&bh[n]);

    float4 r;
    r.x = tanhf(p0.x + p1.x + xv.x + bb.x);
    r.y = tanhf(p0.y + p1.y + xv.y + bb.y);
    r.z = tanhf(p0.z + p1.z + xv.z + bb.z);
    r.w = tanhf(p0.w + p1.w + xv.w + bb.w);
    *reinterpret_cast<float4*>(&hout[idx]) = r;
}

// ---------------------------------------------------------------------------
// Launch
// inputs: 0=x [T,B,IN], 1=h [B,H], 2=Wi_w [H,IN], 3=Wi_b [H],
//         4=Wh_w [H,H], 5=Wh_b [H];  output: hiddens [T,B,H]
// ---------------------------------------------------------------------------
extern "C" void kernel_launch(void* const* d_in, const int* in_sizes, int n_in,
                              void* d_out, int out_size) {
    const float* x   = (const float*)d_in[0];
    const float* h0  = (const float*)d_in[1];
    const float* Wi  = (const float*)d_in[2];
    const float* bi  = (const float*)d_in[3];
    const float* Wh  = (const float*)d_in[4];
    const float* bh  = (const float*)d_in[5];
    float* out = (float*)d_out;

    // Phase 1: xi for all timesteps, written straight into d_out
    gemm_xi_kernel<<<dim3(H_DIM / 128, M1 / 128), 256>>>(x, Wi, bi, out);

    // Phase 2: sequential recurrence, in place on d_out
    for (int t = 0; t < T_DIM; t++) {
        const float* hprev = (t == 0) ? h0 : out + (size_t)(t - 1) * B_DIM * H_DIM;
        float* xt = out + (size_t)t * B_DIM * H_DIM;
        gemm_h_kernel<<<dim3(H_DIM / 64, B_DIM / 64, 2), 256>>>(hprev, Wh);
        step_epilogue_kernel<<<256, 256>>>(xt, bh, xt);
    }
}